// round 1
// baseline (speedup 1.0000x reference)
#include <cuda_runtime.h>
#include <mma.h>
#include <math.h>

using namespace nvcuda;

#define Bb   2
#define SEQ  2048
#define Dd   2048
#define NH   32
#define HD   64
#define NKV  8

// Scratch (no allocation allowed)
__device__ float g_Q [(size_t)Bb * SEQ * NH  * HD];   // [B,S,NH,HD]
__device__ float g_K [(size_t)Bb * SEQ * NKV * HD];   // [B,S,NKV,HD]
__device__ float g_V [(size_t)Bb * SEQ * NKV * HD];
__device__ float g_AO[(size_t)Bb * SEQ * NH  * HD];   // attention output [B,S,NH*HD]

// ---------------------------------------------------------------------------
// NT GEMM: C[M,N] = A[M,K] @ B[N,K]^T   (all fp32 in memory, tf32 MMA)
// Tiles: BM=128, BN=128, BK=32. 256 threads = 8 warps, each warp 64x32.
// ---------------------------------------------------------------------------
#define BM 128
#define BN 128
#define BK 32
#define LDS 40   // smem leading dim (floats): 40*4=160B, multiple of 16B

__global__ __launch_bounds__(256)
void gemm_nt(const float* __restrict__ A, const float* __restrict__ B,
             float* __restrict__ C, int M, int N, int K) {
    __shared__ float As[BM * LDS];
    __shared__ float Bs[BN * LDS];

    int tid = threadIdx.x;
    int m0 = blockIdx.y * BM;
    int n0 = blockIdx.x * BN;
    int w  = tid >> 5;
    int wm = (w & 1) * 64;    // warp row offset
    int wn = (w >> 1) * 32;   // warp col offset

    wmma::fragment<wmma::accumulator, 16, 16, 8, float> acc[4][2];
    #pragma unroll
    for (int i = 0; i < 4; i++)
        #pragma unroll
        for (int j = 0; j < 2; j++)
            wmma::fill_fragment(acc[i][j], 0.0f);

    for (int kt = 0; kt < K; kt += BK) {
        // cooperative load: 128x32 floats each for A and B (float4)
        #pragma unroll
        for (int i = 0; i < 4; i++) {
            int idx = tid + i * 256;       // 0..1023
            int r = idx >> 3;
            int c = (idx & 7) * 4;
            float4 av = *(const float4*)(A + (size_t)(m0 + r) * K + kt + c);
            *(float4*)(As + r * LDS + c) = av;
            float4 bv = *(const float4*)(B + (size_t)(n0 + r) * K + kt + c);
            *(float4*)(Bs + r * LDS + c) = bv;
        }
        __syncthreads();

        #pragma unroll
        for (int kk = 0; kk < BK; kk += 8) {
            wmma::fragment<wmma::matrix_a, 16, 16, 8, wmma::precision::tf32, wmma::row_major> af[4];
            wmma::fragment<wmma::matrix_b, 16, 16, 8, wmma::precision::tf32, wmma::col_major> bf[2];
            #pragma unroll
            for (int i = 0; i < 4; i++) {
                wmma::load_matrix_sync(af[i], As + (wm + i * 16) * LDS + kk, LDS);
                #pragma unroll
                for (int t = 0; t < af[i].num_elements; t++)
                    af[i].x[t] = wmma::__float_to_tf32(af[i].x[t]);
            }
            #pragma unroll
            for (int j = 0; j < 2; j++) {
                wmma::load_matrix_sync(bf[j], Bs + (wn + j * 16) * LDS + kk, LDS);
                #pragma unroll
                for (int t = 0; t < bf[j].num_elements; t++)
                    bf[j].x[t] = wmma::__float_to_tf32(bf[j].x[t]);
            }
            #pragma unroll
            for (int i = 0; i < 4; i++)
                #pragma unroll
                for (int j = 0; j < 2; j++)
                    wmma::mma_sync(acc[i][j], af[i], bf[j], acc[i][j]);
        }
        __syncthreads();
    }

    #pragma unroll
    for (int i = 0; i < 4; i++)
        #pragma unroll
        for (int j = 0; j < 2; j++)
            wmma::store_matrix_sync(C + (size_t)(m0 + wm + i * 16) * N + n0 + wn + j * 16,
                                    acc[i][j], N, wmma::mem_row_major);
}

// ---------------------------------------------------------------------------
// RoPE in-place on [B,S,nheads,HD]. One thread per (b,s,h,d<32) pair.
// ---------------------------------------------------------------------------
__global__ void rope_kernel(float* __restrict__ X, int nheads, int total) {
    int idx = blockIdx.x * blockDim.x + threadIdx.x;
    if (idx >= total) return;
    int d = idx & 31;
    int h = (idx >> 5) % nheads;
    int s = (idx / (32 * nheads)) % SEQ;
    int b = idx / (32 * nheads * SEQ);

    float inv = powf(10000.0f, -(float)d / 32.0f);
    float f = (float)s * inv;
    float sn, cs;
    sincosf(f, &sn, &cs);

    size_t base = (((size_t)b * SEQ + s) * nheads + h) * HD;
    float x1 = X[base + d];
    float x2 = X[base + d + 32];
    X[base + d]      = x1 * cs - x2 * sn;
    X[base + d + 32] = x2 * cs + x1 * sn;
}

// ---------------------------------------------------------------------------
// Causal flash attention (GQA). Block = (qtile64, head, batch). 128 threads.
// Online softmax; QK^T and P*V via tf32 wmma with smem staging.
// ---------------------------------------------------------------------------
#define ALD 72   // 72*4=288B, multiple of 16B

__global__ __launch_bounds__(128)
void attn_kernel(const float* __restrict__ Q, const float* __restrict__ Kg,
                 const float* __restrict__ Vg, float* __restrict__ AO) {
    extern __shared__ float sm[];
    float* Qs   = sm;
    float* Ks   = Qs + 64 * ALD;
    float* Vs   = Ks + 64 * ALD;
    float* Ps   = Vs + 64 * ALD;   // scores, overwritten in place by probs
    float* Os   = Ps + 64 * ALD;
    float* mrow = Os + 64 * ALD;
    float* lrow = mrow + 64;

    int tid = threadIdx.x;
    int q0 = blockIdx.x * 64;
    int h  = blockIdx.y;
    int b  = blockIdx.z;
    int kvh = h >> 2;   // NREP = 4
    int w = tid >> 5;

    // load Q tile (row stride NH*HD in gmem)
    for (int i = tid; i < 64 * 16; i += 128) {
        int r = i >> 4, c = (i & 15) * 4;
        *(float4*)(Qs + r * ALD + c) =
            *(const float4*)(Q + (((size_t)(b * SEQ + q0 + r)) * NH + h) * HD + c);
    }
    for (int i = tid; i < 64 * ALD; i += 128) Os[i] = 0.0f;
    if (tid < 64) { mrow[tid] = -3e38f; lrow[tid] = 0.0f; }
    __syncthreads();

    int jmax = q0 >> 6;
    for (int j = 0; j <= jmax; j++) {
        int k0 = j * 64;
        // load K and V tiles (row stride NKV*HD)
        for (int i = tid; i < 64 * 16; i += 128) {
            int r = i >> 4, c = (i & 15) * 4;
            size_t g = (((size_t)(b * SEQ + k0 + r)) * NKV + kvh) * HD + c;
            *(float4*)(Ks + r * ALD + c) = *(const float4*)(Kg + g);
            *(float4*)(Vs + r * ALD + c) = *(const float4*)(Vg + g);
        }
        __syncthreads();

        // S = Q K^T  (64x64, warp w computes rows w*16..w*16+15)
        {
            wmma::fragment<wmma::accumulator, 16, 16, 8, float> sacc[4];
            #pragma unroll
            for (int n = 0; n < 4; n++) wmma::fill_fragment(sacc[n], 0.0f);
            #pragma unroll
            for (int kk = 0; kk < 64; kk += 8) {
                wmma::fragment<wmma::matrix_a, 16, 16, 8, wmma::precision::tf32, wmma::row_major> af;
                wmma::load_matrix_sync(af, Qs + (w * 16) * ALD + kk, ALD);
                #pragma unroll
                for (int t = 0; t < af.num_elements; t++) af.x[t] = wmma::__float_to_tf32(af.x[t]);
                #pragma unroll
                for (int n = 0; n < 4; n++) {
                    wmma::fragment<wmma::matrix_b, 16, 16, 8, wmma::precision::tf32, wmma::col_major> bf;
                    wmma::load_matrix_sync(bf, Ks + (n * 16) * ALD + kk, ALD);
                    #pragma unroll
                    for (int t = 0; t < bf.num_elements; t++) bf.x[t] = wmma::__float_to_tf32(bf.x[t]);
                    wmma::mma_sync(sacc[n], af, bf, sacc[n]);
                }
            }
            #pragma unroll
            for (int n = 0; n < 4; n++)
                wmma::store_matrix_sync(Ps + (w * 16) * ALD + n * 16, sacc[n], ALD, wmma::mem_row_major);
        }
        __syncthreads();

        // online softmax update (2 threads per row, 32 cols each)
        {
            int r = tid >> 1;
            int halfo = (tid & 1) * 32;
            int qpos = q0 + r;
            bool diag = (j == jmax);
            float sv[32];
            float mloc = -3e38f;
            #pragma unroll
            for (int c = 0; c < 32; c++) {
                int col = halfo + c;
                float s = Ps[r * ALD + col] * 0.125f;   // 1/sqrt(64)
                if (diag && (k0 + col > qpos)) s = -3e38f;
                sv[c] = s;
                mloc = fmaxf(mloc, s);
            }
            mloc = fmaxf(mloc, __shfl_xor_sync(0xffffffffu, mloc, 1));
            float mold = mrow[r];
            float mnew = fmaxf(mold, mloc);
            float alpha = __expf(mold - mnew);
            float sum = 0.0f;
            #pragma unroll
            for (int c = 0; c < 32; c++) {
                float p = __expf(sv[c] - mnew);
                Ps[r * ALD + halfo + c] = p;
                sum += p;
            }
            sum += __shfl_xor_sync(0xffffffffu, sum, 1);
            if ((tid & 1) == 0) { lrow[r] = lrow[r] * alpha + sum; mrow[r] = mnew; }
            #pragma unroll
            for (int c = 0; c < 32; c++) Os[r * ALD + halfo + c] *= alpha;
        }
        __syncthreads();

        // O += P V
        {
            wmma::fragment<wmma::accumulator, 16, 16, 8, float> oacc[4];
            #pragma unroll
            for (int n = 0; n < 4; n++)
                wmma::load_matrix_sync(oacc[n], Os + (w * 16) * ALD + n * 16, ALD, wmma::mem_row_major);
            #pragma unroll
            for (int kk = 0; kk < 64; kk += 8) {
                wmma::fragment<wmma::matrix_a, 16, 16, 8, wmma::precision::tf32, wmma::row_major> af;
                wmma::load_matrix_sync(af, Ps + (w * 16) * ALD + kk, ALD);
                #pragma unroll
                for (int t = 0; t < af.num_elements; t++) af.x[t] = wmma::__float_to_tf32(af.x[t]);
                #pragma unroll
                for (int n = 0; n < 4; n++) {
                    wmma::fragment<wmma::matrix_b, 16, 16, 8, wmma::precision::tf32, wmma::row_major> bf;
                    wmma::load_matrix_sync(bf, Vs + kk * ALD + n * 16, ALD);
                    #pragma unroll
                    for (int t = 0; t < bf.num_elements; t++) bf.x[t] = wmma::__float_to_tf32(bf.x[t]);
                    wmma::mma_sync(oacc[n], af, bf, oacc[n]);
                }
            }
            #pragma unroll
            for (int n = 0; n < 4; n++)
                wmma::store_matrix_sync(Os + (w * 16) * ALD + n * 16, oacc[n], ALD, wmma::mem_row_major);
        }
        __syncthreads();
    }

    // epilogue: normalize and write to [B,S,NH*HD]
    for (int i = tid; i < 64 * 64; i += 128) {
        int r = i >> 6, c = i & 63;
        AO[(((size_t)(b * SEQ + q0 + r)) * NH + h) * HD + c] = Os[r * ALD + c] / lrow[r];
    }
}

// ---------------------------------------------------------------------------
extern "C" void kernel_launch(void* const* d_in, const int* in_sizes, int n_in,
                              void* d_out, int out_size) {
    const float* X  = (const float*)d_in[0];
    const float* Wq = (const float*)d_in[1];
    const float* Wk = (const float*)d_in[2];
    const float* Wv = (const float*)d_in[3];
    const float* Wo = (const float*)d_in[4];
    // d_in[5] = attention_mask: pure causal, applied analytically, never read.
    float* out = (float*)d_out;

    float *pQ, *pK, *pV, *pAO;
    cudaGetSymbolAddress((void**)&pQ,  g_Q);
    cudaGetSymbolAddress((void**)&pK,  g_K);
    cudaGetSymbolAddress((void**)&pV,  g_V);
    cudaGetSymbolAddress((void**)&pAO, g_AO);

    const int M = Bb * SEQ;  // 4096

    gemm_nt<<<dim3((NH * HD) / BN,  M / BM), 256>>>(X, Wq, pQ, M, NH * HD, Dd);
    gemm_nt<<<dim3((NKV * HD) / BN, M / BM), 256>>>(X, Wk, pK, M, NKV * HD, Dd);
    gemm_nt<<<dim3((NKV * HD) / BN, M / BM), 256>>>(X, Wv, pV, M, NKV * HD, Dd);

    int nq = Bb * SEQ * NH * 32;
    rope_kernel<<<(nq + 255) / 256, 256>>>(pQ, NH, nq);
    int nk = Bb * SEQ * NKV * 32;
    rope_kernel<<<(nk + 255) / 256, 256>>>(pK, NKV, nk);

    int smem = (5 * 64 * ALD + 128) * (int)sizeof(float);
    cudaFuncSetAttribute(attn_kernel, cudaFuncAttributeMaxDynamicSharedMemorySize, smem);
    attn_kernel<<<dim3(SEQ / 64, NH, Bb), 128, smem>>>(pQ, pK, pV, pAO);

    gemm_nt<<<dim3(Dd / BN, M / BM), 256>>>(pAO, Wo, out, M, Dd, NH * HD);
}

// round 3
// speedup vs baseline: 1.1188x; 1.1188x over previous
#include <cuda_runtime.h>
#include <mma.h>
#include <math.h>
#include <cstdint>
#include <stdint.h>

using namespace nvcuda;

#define Bb   2
#define SEQ  2048
#define Dd   2048
#define NH   32
#define HD   64
#define NKV  8

// Scratch (no allocation allowed)
__device__ float g_Q [(size_t)Bb * SEQ * NH  * HD];
__device__ float g_K [(size_t)Bb * SEQ * NKV * HD];
__device__ float g_V [(size_t)Bb * SEQ * NKV * HD];
__device__ float g_AO[(size_t)Bb * SEQ * NH  * HD];

__device__ __forceinline__ void cp16(void* smem, const void* gmem) {
    unsigned int s = (unsigned int)__cvta_generic_to_shared(smem);
    asm volatile("cp.async.cg.shared.global [%0], [%1], 16;" :: "r"(s), "l"(gmem));
}
__device__ __forceinline__ void cp_commit() {
    asm volatile("cp.async.commit_group;");
}
template<int N> __device__ __forceinline__ void cp_wait() {
    asm volatile("cp.async.wait_group %0;" :: "n"(N));
}

// ---------------------------------------------------------------------------
// Pipelined NT GEMM: C[M,N] = A[M,K] @ B[N,K]^T, tf32 MMA, 3-stage cp.async.
// BM=BN=128, BK=32, 256 threads (8 warps, each 64x32).
// ---------------------------------------------------------------------------
#define BM 128
#define BN 128
#define BK 32
#define PADK 36      // smem row stride (floats); 36*4=144B (16B mult, +4 bank shift)
#define STAGES 3
#define TILE_F (BM * PADK)

__device__ __forceinline__ void gemm_load_tile(float* As, float* Bs,
        const float* __restrict__ A, const float* __restrict__ B,
        int m0, int n0, int kt, int K, int tid) {
    #pragma unroll
    for (int i = 0; i < 4; i++) {
        int idx = tid + i * 256;       // 0..1023
        int r = idx >> 3;
        int c = (idx & 7) * 4;
        cp16(As + r * PADK + c, A + (size_t)(m0 + r) * K + kt + c);
        cp16(Bs + r * PADK + c, B + (size_t)(n0 + r) * K + kt + c);
    }
}

__global__ __launch_bounds__(256)
void gemm_nt(const float* __restrict__ A, const float* __restrict__ B,
             float* __restrict__ C, int M, int N, int K) {
    extern __shared__ float smem[];
    float* As = smem;                       // [STAGES][TILE_F]
    float* Bs = smem + STAGES * TILE_F;     // [STAGES][TILE_F]

    int tid = threadIdx.x;
    int m0 = blockIdx.y * BM;
    int n0 = blockIdx.x * BN;
    int w  = tid >> 5;
    int wm = (w & 1) * 64;
    int wn = (w >> 1) * 32;

    wmma::fragment<wmma::accumulator, 16, 16, 8, float> acc[4][2];
    #pragma unroll
    for (int i = 0; i < 4; i++)
        #pragma unroll
        for (int j = 0; j < 2; j++)
            wmma::fill_fragment(acc[i][j], 0.0f);

    const int num_k = K / BK;

    #pragma unroll
    for (int s = 0; s < STAGES - 1; s++) {
        gemm_load_tile(As + s * TILE_F, Bs + s * TILE_F, A, B, m0, n0, s * BK, K, tid);
        cp_commit();
    }

    for (int kt = 0; kt < num_k; kt++) {
        cp_wait<STAGES - 2>();
        __syncthreads();

        int buf = kt % STAGES;
        float* Asb = As + buf * TILE_F;
        float* Bsb = Bs + buf * TILE_F;

        // prefetch tile kt+STAGES-1 into the buffer freed at iteration kt-1
        int nk = kt + STAGES - 1;
        if (nk < num_k) {
            gemm_load_tile(As + (nk % STAGES) * TILE_F, Bs + (nk % STAGES) * TILE_F,
                           A, B, m0, n0, nk * BK, K, tid);
        }
        cp_commit();

        #pragma unroll
        for (int kk = 0; kk < BK; kk += 8) {
            wmma::fragment<wmma::matrix_a, 16, 16, 8, wmma::precision::tf32, wmma::row_major> af[4];
            wmma::fragment<wmma::matrix_b, 16, 16, 8, wmma::precision::tf32, wmma::col_major> bf[2];
            #pragma unroll
            for (int i = 0; i < 4; i++) {
                wmma::load_matrix_sync(af[i], Asb + (wm + i * 16) * PADK + kk, PADK);
                #pragma unroll
                for (int t = 0; t < af[i].num_elements; t++)
                    af[i].x[t] = wmma::__float_to_tf32(af[i].x[t]);
            }
            #pragma unroll
            for (int j = 0; j < 2; j++) {
                wmma::load_matrix_sync(bf[j], Bsb + (wn + j * 16) * PADK + kk, PADK);
                #pragma unroll
                for (int t = 0; t < bf[j].num_elements; t++)
                    bf[j].x[t] = wmma::__float_to_tf32(bf[j].x[t]);
            }
            #pragma unroll
            for (int i = 0; i < 4; i++)
                #pragma unroll
                for (int j = 0; j < 2; j++)
                    wmma::mma_sync(acc[i][j], af[i], bf[j], acc[i][j]);
        }
        __syncthreads();
    }

    #pragma unroll
    for (int i = 0; i < 4; i++)
        #pragma unroll
        for (int j = 0; j < 2; j++)
            wmma::store_matrix_sync(C + (size_t)(m0 + wm + i * 16) * N + n0 + wn + j * 16,
                                    acc[i][j], N, wmma::mem_row_major);
}

// ---------------------------------------------------------------------------
// RoPE in-place on [B,S,nheads,HD].
// ---------------------------------------------------------------------------
__global__ void rope_kernel(float* __restrict__ X, int nheads, int total) {
    int idx = blockIdx.x * blockDim.x + threadIdx.x;
    if (idx >= total) return;
    int d = idx & 31;
    int h = (idx >> 5) % nheads;
    int s = (idx / (32 * nheads)) % SEQ;
    int b = idx / (32 * nheads * SEQ);

    float inv = powf(10000.0f, -(float)d / 32.0f);
    float f = (float)s * inv;
    float sn, cs;
    sincosf(f, &sn, &cs);

    size_t base = (((size_t)b * SEQ + s) * nheads + h) * HD;
    float x1 = X[base + d];
    float x2 = X[base + d + 32];
    X[base + d]      = x1 * cs - x2 * sn;
    X[base + d + 32] = x2 * cs + x1 * sn;
}

// ---------------------------------------------------------------------------
// Causal flash attention (GQA). BQ=128 q rows/block, 256 threads (8 warps).
// KV tiles of 64 rows, double-buffered via cp.async.
// ---------------------------------------------------------------------------
#define ALD 68   // 68*4=272B: 16B multiple, 4-bank row shift
#define BQ  128

__global__ __launch_bounds__(256)
void attn_kernel(const float* __restrict__ Q, const float* __restrict__ Kg,
                 const float* __restrict__ Vg, float* __restrict__ AO) {
    extern __shared__ float sm[];
    float* Qs   = sm;                        // BQ  * ALD
    float* Ks   = Qs + BQ * ALD;             // 2 * 64 * ALD
    float* Vs   = Ks + 2 * 64 * ALD;         // 2 * 64 * ALD
    float* Ps   = Vs + 2 * 64 * ALD;         // BQ  * ALD
    float* Os   = Ps + BQ * ALD;             // BQ  * ALD
    float* mrow = Os + BQ * ALD;             // BQ
    float* lrow = mrow + BQ;                 // BQ

    int tid = threadIdx.x;
    int q0 = blockIdx.x * BQ;
    int h  = blockIdx.y;
    int b  = blockIdx.z;
    int kvh = h >> 2;   // NREP = 4
    int w = tid >> 5;

    // Q tile load via cp.async: BQ rows x 16 float4
    for (int i = tid; i < BQ * 16; i += 256) {
        int r = i >> 4, c = (i & 15) * 4;
        cp16(Qs + r * ALD + c,
             Q + (((size_t)(b * SEQ + q0 + r)) * NH + h) * HD + c);
    }
    cp_commit();

    // KV tile 0
    for (int i = tid; i < 64 * 16; i += 256) {
        int r = i >> 4, c = (i & 15) * 4;
        size_t g = (((size_t)(b * SEQ + r)) * NKV + kvh) * HD + c;
        cp16(Ks + r * ALD + c, Kg + g);
        cp16(Vs + r * ALD + c, Vg + g);
    }
    cp_commit();

    for (int i = tid; i < BQ * ALD; i += 256) Os[i] = 0.0f;
    if (tid < BQ) { mrow[tid] = -3e38f; lrow[tid] = 0.0f; }

    int jmax = (q0 + BQ - 1) >> 6;
    for (int j = 0; j <= jmax; j++) {
        int k0 = j * 64;
        int buf = j & 1;
        float* Kb = Ks + buf * 64 * ALD;
        float* Vb = Vs + buf * 64 * ALD;

        cp_wait<0>();
        __syncthreads();

        // prefetch next KV tile into the other buffer
        if (j < jmax) {
            float* Kn = Ks + (buf ^ 1) * 64 * ALD;
            float* Vn = Vs + (buf ^ 1) * 64 * ALD;
            int kn = (j + 1) * 64;
            for (int i = tid; i < 64 * 16; i += 256) {
                int r = i >> 4, c = (i & 15) * 4;
                size_t g = (((size_t)(b * SEQ + kn + r)) * NKV + kvh) * HD + c;
                cp16(Kn + r * ALD + c, Kg + g);
                cp16(Vn + r * ALD + c, Vg + g);
            }
        }
        cp_commit();

        // S = Q K^T : warp w computes rows w*16..w*16+15, 64 cols
        {
            wmma::fragment<wmma::accumulator, 16, 16, 8, float> sacc[4];
            #pragma unroll
            for (int n = 0; n < 4; n++) wmma::fill_fragment(sacc[n], 0.0f);
            #pragma unroll
            for (int kk = 0; kk < 64; kk += 8) {
                wmma::fragment<wmma::matrix_a, 16, 16, 8, wmma::precision::tf32, wmma::row_major> af;
                wmma::load_matrix_sync(af, Qs + (w * 16) * ALD + kk, ALD);
                #pragma unroll
                for (int t = 0; t < af.num_elements; t++) af.x[t] = wmma::__float_to_tf32(af.x[t]);
                #pragma unroll
                for (int n = 0; n < 4; n++) {
                    wmma::fragment<wmma::matrix_b, 16, 16, 8, wmma::precision::tf32, wmma::col_major> bf;
                    wmma::load_matrix_sync(bf, Kb + (n * 16) * ALD + kk, ALD);
                    #pragma unroll
                    for (int t = 0; t < bf.num_elements; t++) bf.x[t] = wmma::__float_to_tf32(bf.x[t]);
                    wmma::mma_sync(sacc[n], af, bf, sacc[n]);
                }
            }
            #pragma unroll
            for (int n = 0; n < 4; n++)
                wmma::store_matrix_sync(Ps + (w * 16) * ALD + n * 16, sacc[n], ALD, wmma::mem_row_major);
        }
        __syncthreads();

        // online softmax (2 threads per row, 32 cols each)
        {
            int r = tid >> 1;
            int halfo = (tid & 1) * 32;
            int qpos = q0 + r;
            float sv[32];
            float mloc = -3e38f;
            #pragma unroll
            for (int c = 0; c < 32; c++) {
                int col = halfo + c;
                float s = Ps[r * ALD + col] * 0.125f;       // 1/sqrt(64)
                if (k0 + col > qpos) s = -3e38f;
                sv[c] = s;
                mloc = fmaxf(mloc, s);
            }
            mloc = fmaxf(mloc, __shfl_xor_sync(0xffffffffu, mloc, 1));
            float mold = mrow[r];
            float mnew = fmaxf(mold, mloc);
            float alpha = __expf(mold - mnew);
            float sum = 0.0f;
            #pragma unroll
            for (int c = 0; c < 32; c++) {
                float p = __expf(sv[c] - mnew);
                Ps[r * ALD + halfo + c] = p;
                sum += p;
            }
            sum += __shfl_xor_sync(0xffffffffu, sum, 1);
            if ((tid & 1) == 0) { lrow[r] = lrow[r] * alpha + sum; mrow[r] = mnew; }
            #pragma unroll
            for (int c = 0; c < 32; c++) Os[r * ALD + halfo + c] *= alpha;
        }
        __syncthreads();

        // O += P V
        {
            wmma::fragment<wmma::accumulator, 16, 16, 8, float> oacc[4];
            #pragma unroll
            for (int n = 0; n < 4; n++)
                wmma::load_matrix_sync(oacc[n], Os + (w * 16) * ALD + n * 16, ALD, wmma::mem_row_major);
            #pragma unroll
            for (int kk = 0; kk < 64; kk += 8) {
                wmma::fragment<wmma::matrix_a, 16, 16, 8, wmma::precision::tf32, wmma::row_major> af;
                wmma::load_matrix_sync(af, Ps + (w * 16) * ALD + kk, ALD);
                #pragma unroll
                for (int t = 0; t < af.num_elements; t++) af.x[t] = wmma::__float_to_tf32(af.x[t]);
                #pragma unroll
                for (int n = 0; n < 4; n++) {
                    wmma::fragment<wmma::matrix_b, 16, 16, 8, wmma::precision::tf32, wmma::row_major> bf;
                    wmma::load_matrix_sync(bf, Vb + kk * ALD + n * 16, ALD);
                    #pragma unroll
                    for (int t = 0; t < bf.num_elements; t++) bf.x[t] = wmma::__float_to_tf32(bf.x[t]);
                    wmma::mma_sync(oacc[n], af, bf, oacc[n]);
                }
            }
            #pragma unroll
            for (int n = 0; n < 4; n++)
                wmma::store_matrix_sync(Os + (w * 16) * ALD + n * 16, oacc[n], ALD, wmma::mem_row_major);
        }
        __syncthreads();
    }

    // epilogue: normalize and write [B,S,NH*HD]
    for (int i = tid; i < BQ * 64; i += 256) {
        int r = i >> 6, c = i & 63;
        AO[(((size_t)(b * SEQ + q0 + r)) * NH + h) * HD + c] = Os[r * ALD + c] / lrow[r];
    }
}

// ---------------------------------------------------------------------------
extern "C" void kernel_launch(void* const* d_in, const int* in_sizes, int n_in,
                              void* d_out, int out_size) {
    const float* X  = (const float*)d_in[0];
    const float* Wq = (const float*)d_in[1];
    const float* Wk = (const float*)d_in[2];
    const float* Wv = (const float*)d_in[3];
    const float* Wo = (const float*)d_in[4];
    // d_in[5] = attention_mask: pure causal, applied analytically, never read.
    float* out = (float*)d_out;

    float *pQ, *pK, *pV, *pAO;
    cudaGetSymbolAddress((void**)&pQ,  g_Q);
    cudaGetSymbolAddress((void**)&pK,  g_K);
    cudaGetSymbolAddress((void**)&pV,  g_V);
    cudaGetSymbolAddress((void**)&pAO, g_AO);

    const int M = Bb * SEQ;  // 4096

    int gsmem = STAGES * TILE_F * 2 * (int)sizeof(float);   // 110592 B
    cudaFuncSetAttribute(gemm_nt, cudaFuncAttributeMaxDynamicSharedMemorySize, gsmem);

    gemm_nt<<<dim3((NH * HD) / BN,  M / BM), 256, gsmem>>>(X, Wq, pQ, M, NH * HD, Dd);
    gemm_nt<<<dim3((NKV * HD) / BN, M / BM), 256, gsmem>>>(X, Wk, pK, M, NKV * HD, Dd);
    gemm_nt<<<dim3((NKV * HD) / BN, M / BM), 256, gsmem>>>(X, Wv, pV, M, NKV * HD, Dd);

    int nq = Bb * SEQ * NH * 32;
    rope_kernel<<<(nq + 255) / 256, 256>>>(pQ, NH, nq);
    int nk = Bb * SEQ * NKV * 32;
    rope_kernel<<<(nk + 255) / 256, 256>>>(pK, NKV, nk);

    int asmem = (3 * BQ * ALD + 4 * 64 * ALD + 2 * BQ) * (int)sizeof(float);
    cudaFuncSetAttribute(attn_kernel, cudaFuncAttributeMaxDynamicSharedMemorySize, asmem);
    attn_kernel<<<dim3(SEQ / BQ, NH, Bb), 256, asmem>>>(pQ, pK, pV, pAO);

    gemm_nt<<<dim3(Dd / BN, M / BM), 256, gsmem>>>(pAO, Wo, out, M, Dd, NH * HD);
}

// round 4
// speedup vs baseline: 1.1787x; 1.0536x over previous
#include <cuda_runtime.h>
#include <mma.h>
#include <math.h>
#include <cstdint>
#include <stdint.h>

using namespace nvcuda;

#define Bb   2
#define SEQ  2048
#define Dd   2048
#define NH   32
#define HD   64
#define NKV  8

// Scratch (no allocation allowed)
__device__ float g_Q  [(size_t)Bb * SEQ * NH  * HD];
__device__ float g_K  [(size_t)Bb * SEQ * NKV * HD];
__device__ float g_V  [(size_t)Bb * SEQ * NKV * HD];
__device__ float g_AO [(size_t)Bb * SEQ * NH  * HD];
// tf32-pre-rounded copies of inputs
__device__ float g_Xr [(size_t)Bb * SEQ * Dd];
__device__ float g_Wqr[(size_t)NH  * HD * Dd];
__device__ float g_Wkr[(size_t)NKV * HD * Dd];
__device__ float g_Wvr[(size_t)NKV * HD * Dd];
__device__ float g_Wor[(size_t)Dd * NH * HD];

__device__ __forceinline__ void cp16(void* smem, const void* gmem) {
    unsigned int s = (unsigned int)__cvta_generic_to_shared(smem);
    asm volatile("cp.async.cg.shared.global [%0], [%1], 16;" :: "r"(s), "l"(gmem));
}
__device__ __forceinline__ void cp_commit() {
    asm volatile("cp.async.commit_group;");
}
template<int N> __device__ __forceinline__ void cp_wait() {
    asm volatile("cp.async.wait_group %0;" :: "n"(N));
}

// ---------------------------------------------------------------------------
// tf32 pre-rounding pass (float4 vectorized)
// ---------------------------------------------------------------------------
__global__ void round_tf32_kernel(const float* __restrict__ in,
                                  float* __restrict__ out, int n4) {
    int i = blockIdx.x * blockDim.x + threadIdx.x;
    if (i >= n4) return;
    float4 v = ((const float4*)in)[i];
    v.x = wmma::__float_to_tf32(v.x);
    v.y = wmma::__float_to_tf32(v.y);
    v.z = wmma::__float_to_tf32(v.z);
    v.w = wmma::__float_to_tf32(v.w);
    ((float4*)out)[i] = v;
}

// ---------------------------------------------------------------------------
// Pipelined NT GEMM: C[M,N] = A[M,K] @ B[N,K]^T, tf32 MMA, 3-stage cp.async.
// Inputs are pre-rounded to tf32 -> no in-loop conversions.
// ROUND: round the outputs to tf32 (for intermediates consumed by later MMAs).
// ---------------------------------------------------------------------------
#define BM 128
#define BN 128
#define BK 32
#define PADK 36
#define STAGES 3
#define TILE_F (BM * PADK)

__device__ __forceinline__ void gemm_load_tile(float* As, float* Bs,
        const float* __restrict__ A, const float* __restrict__ B,
        int m0, int n0, int kt, int K, int tid) {
    #pragma unroll
    for (int i = 0; i < 4; i++) {
        int idx = tid + i * 256;
        int r = idx >> 3;
        int c = (idx & 7) * 4;
        cp16(As + r * PADK + c, A + (size_t)(m0 + r) * K + kt + c);
        cp16(Bs + r * PADK + c, B + (size_t)(n0 + r) * K + kt + c);
    }
}

template<bool ROUND>
__global__ __launch_bounds__(256)
void gemm_nt(const float* __restrict__ A, const float* __restrict__ B,
             float* __restrict__ C, int M, int N, int K) {
    extern __shared__ float smem[];
    float* As = smem;
    float* Bs = smem + STAGES * TILE_F;

    int tid = threadIdx.x;
    int m0 = blockIdx.y * BM;
    int n0 = blockIdx.x * BN;
    int w  = tid >> 5;
    int wm = (w & 1) * 64;
    int wn = (w >> 1) * 32;

    wmma::fragment<wmma::accumulator, 16, 16, 8, float> acc[4][2];
    #pragma unroll
    for (int i = 0; i < 4; i++)
        #pragma unroll
        for (int j = 0; j < 2; j++)
            wmma::fill_fragment(acc[i][j], 0.0f);

    const int num_k = K / BK;

    #pragma unroll
    for (int s = 0; s < STAGES - 1; s++) {
        gemm_load_tile(As + s * TILE_F, Bs + s * TILE_F, A, B, m0, n0, s * BK, K, tid);
        cp_commit();
    }

    for (int kt = 0; kt < num_k; kt++) {
        cp_wait<STAGES - 2>();
        __syncthreads();   // single barrier per iter: also protects prefetch target buf

        int nk = kt + STAGES - 1;
        if (nk < num_k) {
            gemm_load_tile(As + (nk % STAGES) * TILE_F, Bs + (nk % STAGES) * TILE_F,
                           A, B, m0, n0, nk * BK, K, tid);
        }
        cp_commit();

        int buf = kt % STAGES;
        float* Asb = As + buf * TILE_F;
        float* Bsb = Bs + buf * TILE_F;

        #pragma unroll
        for (int kk = 0; kk < BK; kk += 8) {
            wmma::fragment<wmma::matrix_a, 16, 16, 8, wmma::precision::tf32, wmma::row_major> af[4];
            wmma::fragment<wmma::matrix_b, 16, 16, 8, wmma::precision::tf32, wmma::col_major> bf[2];
            #pragma unroll
            for (int i = 0; i < 4; i++)
                wmma::load_matrix_sync(af[i], Asb + (wm + i * 16) * PADK + kk, PADK);
            #pragma unroll
            for (int j = 0; j < 2; j++)
                wmma::load_matrix_sync(bf[j], Bsb + (wn + j * 16) * PADK + kk, PADK);
            #pragma unroll
            for (int i = 0; i < 4; i++)
                #pragma unroll
                for (int j = 0; j < 2; j++)
                    wmma::mma_sync(acc[i][j], af[i], bf[j], acc[i][j]);
        }
    }
    __syncthreads();

    #pragma unroll
    for (int i = 0; i < 4; i++)
        #pragma unroll
        for (int j = 0; j < 2; j++) {
            if (ROUND) {
                #pragma unroll
                for (int t = 0; t < acc[i][j].num_elements; t++)
                    acc[i][j].x[t] = wmma::__float_to_tf32(acc[i][j].x[t]);
            }
            wmma::store_matrix_sync(C + (size_t)(m0 + wm + i * 16) * N + n0 + wn + j * 16,
                                    acc[i][j], N, wmma::mem_row_major);
        }
}

// ---------------------------------------------------------------------------
// RoPE in-place on [B,S,nheads,HD], outputs rounded to tf32.
// ---------------------------------------------------------------------------
__global__ void rope_kernel(float* __restrict__ X, int nheads, int total) {
    int idx = blockIdx.x * blockDim.x + threadIdx.x;
    if (idx >= total) return;
    int d = idx & 31;
    int h = (idx >> 5) % nheads;
    int s = (idx / (32 * nheads)) % SEQ;
    int b = idx / (32 * nheads * SEQ);

    float inv = powf(10000.0f, -(float)d / 32.0f);
    float f = (float)s * inv;
    float sn, cs;
    sincosf(f, &sn, &cs);

    size_t base = (((size_t)b * SEQ + s) * nheads + h) * HD;
    float x1 = X[base + d];
    float x2 = X[base + d + 32];
    X[base + d]      = wmma::__float_to_tf32(x1 * cs - x2 * sn);
    X[base + d + 32] = wmma::__float_to_tf32(x2 * cs + x1 * sn);
}

// ---------------------------------------------------------------------------
// Causal flash attention (GQA). BQ=128 q rows/block, 256 threads (8 warps).
// Warp w owns rows 16w..16w+15 of S/P/O -> only 1 block barrier per KV tile.
// All MMA operands pre-rounded tf32 -> no in-loop conversions.
// ---------------------------------------------------------------------------
#define ALD 68
#define BQ  128

__global__ __launch_bounds__(256)
void attn_kernel(const float* __restrict__ Q, const float* __restrict__ Kg,
                 const float* __restrict__ Vg, float* __restrict__ AO) {
    extern __shared__ float sm[];
    float* Qs   = sm;                        // BQ  * ALD
    float* Ks   = Qs + BQ * ALD;             // 2 * 64 * ALD
    float* Vs   = Ks + 2 * 64 * ALD;         // 2 * 64 * ALD
    float* Ps   = Vs + 2 * 64 * ALD;         // BQ  * ALD
    float* Os   = Ps + BQ * ALD;             // BQ  * ALD
    float* mrow = Os + BQ * ALD;             // BQ
    float* lrow = mrow + BQ;                 // BQ

    int tid = threadIdx.x;
    int q0 = blockIdx.x * BQ;
    int h  = blockIdx.y;
    int b  = blockIdx.z;
    int kvh = h >> 2;   // NREP = 4
    int w = tid >> 5;

    for (int i = tid; i < BQ * 16; i += 256) {
        int r = i >> 4, c = (i & 15) * 4;
        cp16(Qs + r * ALD + c,
             Q + (((size_t)(b * SEQ + q0 + r)) * NH + h) * HD + c);
    }
    cp_commit();

    for (int i = tid; i < 64 * 16; i += 256) {
        int r = i >> 4, c = (i & 15) * 4;
        size_t g = (((size_t)(b * SEQ + r)) * NKV + kvh) * HD + c;
        cp16(Ks + r * ALD + c, Kg + g);
        cp16(Vs + r * ALD + c, Vg + g);
    }
    cp_commit();

    for (int i = tid; i < BQ * ALD; i += 256) Os[i] = 0.0f;
    if (tid < BQ) { mrow[tid] = -3e38f; lrow[tid] = 0.0f; }

    int jmax = (q0 + BQ - 1) >> 6;
    for (int j = 0; j <= jmax; j++) {
        int k0 = j * 64;
        int buf = j & 1;
        float* Kb = Ks + buf * 64 * ALD;
        float* Vb = Vs + buf * 64 * ALD;

        cp_wait<0>();
        __syncthreads();   // single block barrier per KV tile

        if (j < jmax) {
            float* Kn = Ks + (buf ^ 1) * 64 * ALD;
            float* Vn = Vs + (buf ^ 1) * 64 * ALD;
            int kn = (j + 1) * 64;
            for (int i = tid; i < 64 * 16; i += 256) {
                int r = i >> 4, c = (i & 15) * 4;
                size_t g = (((size_t)(b * SEQ + kn + r)) * NKV + kvh) * HD + c;
                cp16(Kn + r * ALD + c, Kg + g);
                cp16(Vn + r * ALD + c, Vg + g);
            }
        }
        cp_commit();

        // S = Q K^T (warp-private rows)
        {
            wmma::fragment<wmma::accumulator, 16, 16, 8, float> sacc[4];
            #pragma unroll
            for (int n = 0; n < 4; n++) wmma::fill_fragment(sacc[n], 0.0f);
            #pragma unroll
            for (int kk = 0; kk < 64; kk += 8) {
                wmma::fragment<wmma::matrix_a, 16, 16, 8, wmma::precision::tf32, wmma::row_major> af;
                wmma::load_matrix_sync(af, Qs + (w * 16) * ALD + kk, ALD);
                #pragma unroll
                for (int n = 0; n < 4; n++) {
                    wmma::fragment<wmma::matrix_b, 16, 16, 8, wmma::precision::tf32, wmma::col_major> bf;
                    wmma::load_matrix_sync(bf, Kb + (n * 16) * ALD + kk, ALD);
                    wmma::mma_sync(sacc[n], af, bf, sacc[n]);
                }
            }
            #pragma unroll
            for (int n = 0; n < 4; n++)
                wmma::store_matrix_sync(Ps + (w * 16) * ALD + n * 16, sacc[n], ALD, wmma::mem_row_major);
        }
        __syncwarp();

        // online softmax (2 threads per row; rows warp-private)
        {
            int r = tid >> 1;
            int halfo = (tid & 1) * 32;
            int qpos = q0 + r;
            float sv[32];
            float mloc = -3e38f;
            #pragma unroll
            for (int c = 0; c < 32; c++) {
                int col = halfo + c;
                float s = Ps[r * ALD + col] * 0.125f;   // 1/sqrt(64)
                if (k0 + col > qpos) s = -3e38f;
                sv[c] = s;
                mloc = fmaxf(mloc, s);
            }
            mloc = fmaxf(mloc, __shfl_xor_sync(0xffffffffu, mloc, 1));
            float mold = mrow[r];
            float mnew = fmaxf(mold, mloc);
            float alpha = __expf(mold - mnew);
            float sum = 0.0f;
            #pragma unroll
            for (int c = 0; c < 32; c++) {
                float p = wmma::__float_to_tf32(__expf(sv[c] - mnew));  // round P; sum the rounded value
                Ps[r * ALD + halfo + c] = p;
                sum += p;
            }
            sum += __shfl_xor_sync(0xffffffffu, sum, 1);
            if ((tid & 1) == 0) { lrow[r] = lrow[r] * alpha + sum; mrow[r] = mnew; }
            #pragma unroll
            for (int c = 0; c < 32; c++) Os[r * ALD + halfo + c] *= alpha;
        }
        __syncwarp();

        // O += P V (warp-private rows)
        {
            wmma::fragment<wmma::accumulator, 16, 16, 8, float> oacc[4];
            #pragma unroll
            for (int n = 0; n < 4; n++)
                wmma::load_matrix_sync(oacc[n], Os + (w * 16) * ALD + n * 16, ALD, wmma::mem_row_major);
            #pragma unroll
            for (int kk = 0; kk < 64; kk += 8) {
                wmma::fragment<wmma::matrix_a, 16, 16, 8, wmma::precision::tf32, wmma::row_major> af;
                wmma::load_matrix_sync(af, Ps + (w * 16) * ALD + kk, ALD);
                #pragma unroll
                for (int n = 0; n < 4; n++) {
                    wmma::fragment<wmma::matrix_b, 16, 16, 8, wmma::precision::tf32, wmma::row_major> bf;
                    wmma::load_matrix_sync(bf, Vb + kk * ALD + n * 16, ALD);
                    wmma::mma_sync(oacc[n], af, bf, oacc[n]);
                }
            }
            #pragma unroll
            for (int n = 0; n < 4; n++)
                wmma::store_matrix_sync(Os + (w * 16) * ALD + n * 16, oacc[n], ALD, wmma::mem_row_major);
        }
        __syncwarp();
    }

    __syncthreads();   // epilogue crosses warp row ownership
    for (int i = tid; i < BQ * 64; i += 256) {
        int r = i >> 6, c = i & 63;
        AO[(((size_t)(b * SEQ + q0 + r)) * NH + h) * HD + c] =
            wmma::__float_to_tf32(Os[r * ALD + c] / lrow[r]);
    }
}

// ---------------------------------------------------------------------------
extern "C" void kernel_launch(void* const* d_in, const int* in_sizes, int n_in,
                              void* d_out, int out_size) {
    const float* X  = (const float*)d_in[0];
    const float* Wq = (const float*)d_in[1];
    const float* Wk = (const float*)d_in[2];
    const float* Wv = (const float*)d_in[3];
    const float* Wo = (const float*)d_in[4];
    // d_in[5] = attention_mask: pure causal, applied analytically, never read.
    float* out = (float*)d_out;

    float *pQ, *pK, *pV, *pAO, *pXr, *pWqr, *pWkr, *pWvr, *pWor;
    cudaGetSymbolAddress((void**)&pQ,   g_Q);
    cudaGetSymbolAddress((void**)&pK,   g_K);
    cudaGetSymbolAddress((void**)&pV,   g_V);
    cudaGetSymbolAddress((void**)&pAO,  g_AO);
    cudaGetSymbolAddress((void**)&pXr,  g_Xr);
    cudaGetSymbolAddress((void**)&pWqr, g_Wqr);
    cudaGetSymbolAddress((void**)&pWkr, g_Wkr);
    cudaGetSymbolAddress((void**)&pWvr, g_Wvr);
    cudaGetSymbolAddress((void**)&pWor, g_Wor);

    const int M = Bb * SEQ;  // 4096

    // launches 0-4: tf32 pre-rounding (also makes launch #5 the big GEMM for ncu -s 5)
    {
        int n4;
        n4 = (Bb * SEQ * Dd) / 4;
        round_tf32_kernel<<<(n4 + 255) / 256, 256>>>(X, pXr, n4);
        n4 = (NH * HD * Dd) / 4;
        round_tf32_kernel<<<(n4 + 255) / 256, 256>>>(Wq, pWqr, n4);
        n4 = (NKV * HD * Dd) / 4;
        round_tf32_kernel<<<(n4 + 255) / 256, 256>>>(Wk, pWkr, n4);
        round_tf32_kernel<<<(n4 + 255) / 256, 256>>>(Wv, pWvr, n4);
        n4 = (Dd * NH * HD) / 4;
        round_tf32_kernel<<<(n4 + 255) / 256, 256>>>(Wo, pWor, n4);
    }

    int gsmem = STAGES * TILE_F * 2 * (int)sizeof(float);   // 110592 B
    cudaFuncSetAttribute(gemm_nt<true>,  cudaFuncAttributeMaxDynamicSharedMemorySize, gsmem);
    cudaFuncSetAttribute(gemm_nt<false>, cudaFuncAttributeMaxDynamicSharedMemorySize, gsmem);

    gemm_nt<true><<<dim3((NH * HD) / BN,  M / BM), 256, gsmem>>>(pXr, pWqr, pQ, M, NH * HD, Dd);
    gemm_nt<true><<<dim3((NKV * HD) / BN, M / BM), 256, gsmem>>>(pXr, pWkr, pK, M, NKV * HD, Dd);
    gemm_nt<true><<<dim3((NKV * HD) / BN, M / BM), 256, gsmem>>>(pXr, pWvr, pV, M, NKV * HD, Dd);

    int nq = Bb * SEQ * NH * 32;
    rope_kernel<<<(nq + 255) / 256, 256>>>(pQ, NH, nq);
    int nk = Bb * SEQ * NKV * 32;
    rope_kernel<<<(nk + 255) / 256, 256>>>(pK, NKV, nk);

    int asmem = (3 * BQ * ALD + 4 * 64 * ALD + 2 * BQ) * (int)sizeof(float);
    cudaFuncSetAttribute(attn_kernel, cudaFuncAttributeMaxDynamicSharedMemorySize, asmem);
    attn_kernel<<<dim3(SEQ / BQ, NH, Bb), 256, asmem>>>(pQ, pK, pV, pAO);

    gemm_nt<false><<<dim3(Dd / BN, M / BM), 256, gsmem>>>(pAO, pWor, out, M, Dd, NH * HD);
}